// round 16
// baseline (speedup 1.0000x reference)
#include <cuda_runtime.h>
#include <cuda_bf16.h>

// SequentialConv: B=8, C=64, H=192, W=256, 3x3, sequential row recurrence.
// Persistent wavefront: 8 batches x 16 width-tiles = 128 CTAs (all resident).
// Round 16: R15 + post-barrier critical-path cuts: (1) phase-2 A-fragments
// preloaded to registers pre-bar; (2) phase-2 MMA chain split 12 -> 2x6;
// (3) tanh.approx.f32 (MUFU) epilogue. Everything else identical to R15.

#define Bb 8
#define Cc 64
#define Hh 192
#define Ww 256
#define NT 16
#define TW 16
#define NTHR 512
#define CIST 72                      // ci stride in row slots (bank-conflict-free)
#define SLOT_ELEMS (18 * CIST)       // bf16 per array per slot

#define AF_U32 36864                 // 4mi * 9khkw * 2hl * 4q * 32lane * 4reg
#define AF_BYTES (AF_U32 * 4)        // 147456
#define BARR_BYTES (5 * SLOT_ELEMS * 2)      // per array (hi / lo)
#define OF_FLOATS (2 * Cc * 16)              // orig-row f32 pingpong (interior)
#define RED_FLOATS (8 * 3 * 32 * 4)          // [mi*2+ni][prod 0..2][lane][4]
#define SMEM_BYTES (AF_BYTES + 2 * BARR_BYTES + OF_FLOATS * 4 + RED_FLOATS * 4)

typedef unsigned int u32;

__device__ int g_flags[Bb * NT];

__global__ void sc_init_flags() {
    int i = threadIdx.x;
    if (i < Bb * NT) g_flags[i] = 0;
}

__device__ __forceinline__ void split_sts(__nv_bfloat16* ph, __nv_bfloat16* pl, float v) {
    __nv_bfloat16 h = __float2bfloat16(v);
    *ph = h;
    *pl = __float2bfloat16(v - __bfloat162float(h));
}

__device__ __forceinline__ float tanh_fast(float x) {
    float y;
    asm("tanh.approx.f32 %0, %1;" : "=f"(y) : "f"(x));
    return y;
}

__device__ __forceinline__ void mma16816(float* d,
                                         u32 a0, u32 a1, u32 a2, u32 a3,
                                         u32 b0, u32 b1) {
    asm("mma.sync.aligned.m16n8k16.row.col.f32.bf16.bf16.f32 "
        "{%0,%1,%2,%3},{%4,%5,%6,%7},{%8,%9},{%0,%1,%2,%3};"
        : "+f"(d[0]), "+f"(d[1]), "+f"(d[2]), "+f"(d[3])
        : "r"(a0), "r"(a1), "r"(a2), "r"(a3), "r"(b0), "r"(b1));
}

// Both-ni plane over this warp's 2 K-chunks: A loaded once, used for 2 B tiles.
#define CONV2Q(d0, d1, SLOT, KH, KW)                                          \
  {                                                                           \
    const int khkw_ = (KH) * 3 + (KW);                                        \
    const __nv_bfloat16* bh0 = BHI + (SLOT) * SLOT_ELEMS + wrow0 + (KW) * CIST;\
    const __nv_bfloat16* bl0 = BLO + (SLOT) * SLOT_ELEMS + wrow0 + (KW) * CIST;\
    const __nv_bfloat16* bh1 = BHI + (SLOT) * SLOT_ELEMS + wrow1 + (KW) * CIST;\
    const __nv_bfloat16* bl1 = BLO + (SLOT) * SLOT_ELEMS + wrow1 + (KW) * CIST;\
    _Pragma("unroll")                                                         \
    for (int j = 0; j < 2; j++) {                                             \
      const int q_ = qb + j;                                                  \
      uint4 ah = AF4[(((mi * 9 + khkw_) * 2 + 0) * 4 + q_) * 32 + lane];      \
      uint4 al = AF4[(((mi * 9 + khkw_) * 2 + 1) * 4 + q_) * 32 + lane];      \
      u32 c0h = *(const u32*)(bh0 + q_ * 16);                                 \
      u32 c1h = *(const u32*)(bh0 + q_ * 16 + 8);                             \
      u32 c0l = *(const u32*)(bl0 + q_ * 16);                                 \
      u32 c1l = *(const u32*)(bl0 + q_ * 16 + 8);                             \
      mma16816(d0, ah.x, ah.y, ah.z, ah.w, c0h, c1h);                         \
      mma16816(d0, ah.x, ah.y, ah.z, ah.w, c0l, c1l);                         \
      mma16816(d0, al.x, al.y, al.z, al.w, c0h, c1h);                         \
      u32 e0h = *(const u32*)(bh1 + q_ * 16);                                 \
      u32 e1h = *(const u32*)(bh1 + q_ * 16 + 8);                             \
      u32 e0l = *(const u32*)(bl1 + q_ * 16);                                 \
      u32 e1l = *(const u32*)(bl1 + q_ * 16 + 8);                             \
      mma16816(d1, ah.x, ah.y, ah.z, ah.w, e0h, e1h);                         \
      mma16816(d1, ah.x, ah.y, ah.z, ah.w, e0l, e1l);                         \
      mma16816(d1, al.x, al.y, al.z, al.w, e0h, e1h);                         \
    }                                                                         \
  }

// One-ni plane over this warp's 2 K-chunks.
#define CONV1NI(dacc, SLOT, KH, KW, WROW)                                     \
  {                                                                           \
    const int khkw_ = (KH) * 3 + (KW);                                        \
    const __nv_bfloat16* bhk = BHI + (SLOT) * SLOT_ELEMS + (WROW) + (KW) * CIST;\
    const __nv_bfloat16* blk = BLO + (SLOT) * SLOT_ELEMS + (WROW) + (KW) * CIST;\
    _Pragma("unroll")                                                         \
    for (int j = 0; j < 2; j++) {                                             \
      const int q_ = qb + j;                                                  \
      uint4 ah = AF4[(((mi * 9 + khkw_) * 2 + 0) * 4 + q_) * 32 + lane];      \
      uint4 al = AF4[(((mi * 9 + khkw_) * 2 + 1) * 4 + q_) * 32 + lane];      \
      u32 b0h = *(const u32*)(bhk + q_ * 16);                                 \
      u32 b1h = *(const u32*)(bhk + q_ * 16 + 8);                             \
      u32 b0l = *(const u32*)(blk + q_ * 16);                                 \
      u32 b1l = *(const u32*)(blk + q_ * 16 + 8);                             \
      mma16816(dacc, ah.x, ah.y, ah.z, ah.w, b0h, b1h);                       \
      mma16816(dacc, ah.x, ah.y, ah.z, ah.w, b0l, b1l);                       \
      mma16816(dacc, al.x, al.y, al.z, al.w, b0h, b1h);                       \
    }                                                                         \
  }

__global__ void __launch_bounds__(NTHR, 1) sc_main(
    const float* __restrict__ X, const float* __restrict__ Wt,
    const float* __restrict__ Bs, float* __restrict__ Out)
{
    extern __shared__ char smem[];
    u32*            AFu = (u32*)smem;                         // A fragments
    const uint4*    AF4 = (const uint4*)smem;
    __nv_bfloat16*  BHI = (__nv_bfloat16*)(smem + AF_BYTES);  // 5 slots [w][ci]
    __nv_bfloat16*  BLO = BHI + 5 * SLOT_ELEMS;
    float*          OF  = (float*)(BLO + 5 * SLOT_ELEMS);     // [2][64][16] f32
    float*          RED = OF + OF_FLOATS;                     // [8][3][32][4] f32

    const int tile = blockIdx.x;
    const int b    = blockIdx.y;
    const int w0   = tile * TW;
    const int tid  = threadIdx.x;
    const int wid  = tid >> 5;
    const int lane = tid & 31;
    const int g    = lane >> 2;
    const int tg   = lane & 3;
    const int grp  = wid >> 3;           // 0 = X, 1 = Y
    const int sub  = wid & 7;
    const int mi   = sub >> 1;           // co-tile 0..3
    const int qh   = sub & 1;            // K-half 0..1
    const int qb   = qh * 2;             // first q of this warp's half
    const int wrow0 = (g) * CIST + 2 * tg;          // ni=0 B base
    const int wrow1 = (8 + g) * CIST + 2 * tg;      // ni=1 B base

    // ---- Init A fragments: exact m16n8k16 A layout, hi/lo split. ----
    for (int i = tid; i < AF_U32; i += NTHR) {
        int r = i & 3; int ln = (i >> 2) & 31; int q = (i >> 7) & 3;
        int hl = (i >> 9) & 1; int t = i >> 10; int khkw = t % 9; int mI = t / 9;
        int gg = ln >> 2, tt = ln & 3;
        int co = mI * 16 + gg + ((r & 1) ? 8 : 0);
        int ci = q * 16 + 2 * tt + ((r & 2) ? 8 : 0);
        int kh = khkw / 3, kw = khkw % 3;
        float f0 = Wt[((co * Cc + ci) * 3 + kh) * 3 + kw];
        float f1 = Wt[((co * Cc + ci + 1) * 3 + kh) * 3 + kw];
        __nv_bfloat16 v0, v1;
        if (hl == 0) { v0 = __float2bfloat16(f0); v1 = __float2bfloat16(f1); }
        else {
            __nv_bfloat16 h0 = __float2bfloat16(f0), h1 = __float2bfloat16(f1);
            v0 = __float2bfloat16(f0 - __bfloat162float(h0));
            v1 = __float2bfloat16(f1 - __bfloat162float(h1));
        }
        AFu[i] = (u32)__bfloat16_as_ushort(v0) | ((u32)__bfloat16_as_ushort(v1) << 16);
    }

    const float* Xb = X   + (size_t)b * Cc * Hh * Ww;
    float*       Ob = Out + (size_t)b * Cc * Hh * Ww;

    // ---- Rows 0,1 (unchanged) -> slots 0,1 (bf16 split, incl halo); Out copy. ----
    for (int r = 0; r < 2; r++) {
        for (int i = tid; i < Cc * 18; i += NTHR) {
            int ci = i / 18, wi = i % 18; int w = w0 - 1 + wi;
            float v = (w >= 0 && w < Ww) ? Xb[(ci * Hh + r) * Ww + w] : 0.f;
            split_sts(&BHI[r * SLOT_ELEMS + wi * CIST + ci],
                      &BLO[r * SLOT_ELEMS + wi * CIST + ci], v);
        }
        for (int i = tid; i < Cc * TW; i += NTHR) {
            int ci = i / TW, wq = i % TW;
            Ob[(ci * Hh + r) * Ww + w0 + wq] = Xb[(ci * Hh + r) * Ww + w0 + wq];
        }
    }
    // Zero slot 2 halo cols (edge tiles keep all upd-slot halos 0 forever).
    if (tid < Cc) {
        BHI[2 * SLOT_ELEMS + tid] = __float2bfloat16(0.f);
        BLO[2 * SLOT_ELEMS + tid] = __float2bfloat16(0.f);
        BHI[2 * SLOT_ELEMS + 17 * CIST + tid] = __float2bfloat16(0.f);
        BLO[2 * SLOT_ELEMS + 17 * CIST + tid] = __float2bfloat16(0.f);
    }
    // Pre-stage orig row 2 (OS slot 3, OF half 0) before the loop.
    for (int i = tid; i < Cc * 18; i += NTHR) {
        int ci = i / 18, wi = i % 18; int w = w0 - 1 + wi;
        float v = (w >= 0 && w < Ww) ? Xb[(ci * Hh + 2) * Ww + w] : 0.f;
        split_sts(&BHI[3 * SLOT_ELEMS + wi * CIST + ci],
                  &BLO[3 * SLOT_ELEMS + wi * CIST + ci], v);
        if (wi >= 1 && wi <= 16) OF[ci * 16 + (wi - 1)] = v;
    }

    const float bs0 = __ldg(&Bs[mi * 16 + g]);
    const float bs1 = __ldg(&Bs[mi * 16 + g + 8]);

    int* myflag = &g_flags[b * NT + tile];
    int* lflag  = (tile > 0)      ? &g_flags[b * NT + tile - 1] : (int*)0;
    int* rflag  = (tile < NT - 1) ? &g_flags[b * NT + tile + 1] : (int*)0;

    __syncthreads();
    if (tid == 0) { __threadfence(); atomicExch(myflag, 1); }   // rows 0,1 published

    const int ytid = tid & 255;   // index within Y group (valid when grp==1)
    // X warps: phase-2 plane constants (compile-time-ish per warp, uniform).
    const int pKW   = (qh == 0) ? 0 : 2;         // halo-dependent kh1 kw
    const int pkhkw = 3 + pKW;
    const int pwrow = (qh == 0) ? wrow0 : wrow1;

    for (int pos = 2; pos < Hh; pos++) {
        const int OS = 3 + (pos & 1);            // orig slot (staged previous step)
        const int US = pos % 3;                  // write slot for updated row pos
        const int S0 = (pos + 1) % 3;            // updated row pos-2
        const int S1 = (pos + 2) % 3;            // updated row pos-1 (halo fresh)

        if (grp == 0) {
            // ---- X: halo + kh0/kh1kw1 (both ni, own q) pre-bar; own-ni halo
            //      plane (all q, A in regs) + reduce + epilogue post-bar. ----
            float hv = 0.f; bool hL = false, hR = false;
            if (tid < Cc && lflag) {
                hL = true;
                while (*(volatile int*)lflag < pos - 1) __nanosleep(32);
                __threadfence();
                hv = __ldcg(&Ob[((size_t)tid * Hh + pos - 1) * Ww + w0 - 1]);
            } else if (tid >= 192 && tid < 192 + Cc && rflag) {
                hR = true;
                int ci = tid - 192;
                while (*(volatile int*)rflag < pos - 1) __nanosleep(32);
                __threadfence();
                hv = __ldcg(&Ob[((size_t)ci * Hh + pos - 1) * Ww + w0 + TW]);
            }

            float a0[4] = {0.f, 0.f, 0.f, 0.f};     // ni=0 accumulator
            float a1[4] = {0.f, 0.f, 0.f, 0.f};     // ni=1 accumulator
            CONV2Q(a0, a1, S0, 0, 0);
            CONV2Q(a0, a1, S0, 0, 1);
            CONV2Q(a0, a1, S0, 0, 2);
            CONV2Q(a0, a1, S1, 1, 1);               // kh1 kw1: interior for both ni

            // Pre-load phase-2 A fragments (own halo plane, all 4 q) to regs.
            uint4 pah[4], pal[4];
            #pragma unroll
            for (int q_ = 0; q_ < 4; q_++) {
                pah[q_] = AF4[(((mi * 9 + pkhkw) * 2 + 0) * 4 + q_) * 32 + lane];
                pal[q_] = AF4[(((mi * 9 + pkhkw) * 2 + 1) * 4 + q_) * 32 + lane];
            }

            // Exchange the other-ni partial (pre-bar complete by construction).
            {
                float* wp = RED + (((mi * 2 + (1 - qh)) * 3 + 0) * 32 + lane) * 4;
                if (qh == 0) *(float4*)wp = make_float4(a1[0], a1[1], a1[2], a1[3]);
                else         *(float4*)wp = make_float4(a0[0], a0[1], a0[2], a0[3]);
            }
            if (hL) split_sts(&BHI[S1 * SLOT_ELEMS + tid], &BLO[S1 * SLOT_ELEMS + tid], hv);
            if (hR) {
                int ci = tid - 192;
                split_sts(&BHI[S1 * SLOT_ELEMS + 17 * CIST + ci],
                          &BLO[S1 * SLOT_ELEMS + 17 * CIST + ci], hv);
            }
            __syncthreads();   // bar-A: halo + all RED partials in place

            // Post-bar: own-ni halo plane, A in regs, 2 independent 6-chains.
            float t0[4] = {0.f, 0.f, 0.f, 0.f};
            float t1[4] = {0.f, 0.f, 0.f, 0.f};
            {
                const __nv_bfloat16* bhk = BHI + S1 * SLOT_ELEMS + pwrow + pKW * CIST;
                const __nv_bfloat16* blk = BLO + S1 * SLOT_ELEMS + pwrow + pKW * CIST;
                #pragma unroll
                for (int q_ = 0; q_ < 4; q_++) {
                    float* tt = (q_ < 2) ? t0 : t1;
                    u32 b0h = *(const u32*)(bhk + q_ * 16);
                    u32 b1h = *(const u32*)(bhk + q_ * 16 + 8);
                    u32 b0l = *(const u32*)(blk + q_ * 16);
                    u32 b1l = *(const u32*)(blk + q_ * 16 + 8);
                    mma16816(tt, pah[q_].x, pah[q_].y, pah[q_].z, pah[q_].w, b0h, b1h);
                    mma16816(tt, pah[q_].x, pah[q_].y, pah[q_].z, pah[q_].w, b0l, b1l);
                    mma16816(tt, pal[q_].x, pal[q_].y, pal[q_].z, pal[q_].w, b0h, b1h);
                }
            }
            float* own = (qh == 0) ? a0 : a1;

            // Reduce the 3 partials (X-other, Y-qh0, Y-qh1) for own half-tile.
            const float* rp = RED + (((mi * 2 + qh) * 3 + 0) * 32 + lane) * 4;
            float4 p0 = *(const float4*)(rp);
            float4 p1 = *(const float4*)(rp + 128);
            float4 p2 = *(const float4*)(rp + 256);
            float d0 = own[0] + t0[0] + t1[0] + p0.x + p1.x + p2.x;
            float d1 = own[1] + t0[1] + t1[1] + p0.y + p1.y + p2.y;
            float d2 = own[2] + t0[2] + t1[2] + p0.z + p1.z + p2.z;
            float d3 = own[3] + t0[3] + t1[3] + p0.w + p1.w + p2.w;

            const int co0 = mi * 16 + g;
            const int wq  = qh * 8 + 2 * tg;
            const float* ofp = OF + (pos & 1) * Cc * 16;
            float r00 = ofp[co0 * 16 + wq]           + tanh_fast(d0 + bs0);
            float r01 = ofp[co0 * 16 + wq + 1]       + tanh_fast(d1 + bs0);
            float r10 = ofp[(co0 + 8) * 16 + wq]     + tanh_fast(d2 + bs1);
            float r11 = ofp[(co0 + 8) * 16 + wq + 1] + tanh_fast(d3 + bs1);

            float* og = Ob + ((size_t)co0 * Hh + pos) * Ww + w0 + wq;
            *(float2*)og = make_float2(r00, r01);
            *(float2*)(og + 8 * (size_t)Hh * Ww) = make_float2(r10, r11);

            __nv_bfloat16* uh = BHI + US * SLOT_ELEMS;
            __nv_bfloat16* ul = BLO + US * SLOT_ELEMS;
            split_sts(&uh[(wq + 1) * CIST + co0],     &ul[(wq + 1) * CIST + co0],     r00);
            split_sts(&uh[(wq + 2) * CIST + co0],     &ul[(wq + 2) * CIST + co0],     r01);
            split_sts(&uh[(wq + 1) * CIST + co0 + 8], &ul[(wq + 1) * CIST + co0 + 8], r10);
            split_sts(&uh[(wq + 2) * CIST + co0 + 8], &ul[(wq + 2) * CIST + co0 + 8], r11);
        } else {
            // ---- Y: prefetch + kh2 (both ni) + kh1 interior (one ni each)
            //      pre-bar; RED push; staging post-bar. ----
            float pv[5];
            if (pos + 1 < Hh) {
                #pragma unroll
                for (int k = 0; k < 5; k++) {
                    int idx = ytid + k * 256;
                    if (idx < Cc * 18) {
                        int ci = idx / 18, wi = idx % 18; int w = w0 - 1 + wi;
                        pv[k] = (w >= 0 && w < Ww) ? __ldg(&Xb[(ci * Hh + pos + 1) * Ww + w]) : 0.f;
                    }
                }
            }

            float a0[4] = {0.f, 0.f, 0.f, 0.f};
            float a1[4] = {0.f, 0.f, 0.f, 0.f};
            CONV2Q(a0, a1, OS, 2, 0);
            CONV2Q(a0, a1, OS, 2, 1);
            CONV2Q(a0, a1, OS, 2, 2);
            CONV1NI(a0, S1, 1, 2, wrow0);   // kh1 ni0 kw2: interior (cols 2..9)
            CONV1NI(a1, S1, 1, 0, wrow1);   // kh1 ni1 kw0: interior (cols 8..15)

            *(float4*)(RED + (((mi * 2 + 0) * 3 + 1 + qh) * 32 + lane) * 4) =
                make_float4(a0[0], a0[1], a0[2], a0[3]);
            *(float4*)(RED + (((mi * 2 + 1) * 3 + 1 + qh) * 32 + lane) * 4) =
                make_float4(a1[0], a1[1], a1[2], a1[3]);
            __syncthreads();   // bar-A

            // Stage orig row pos+1 for the NEXT step.
            if (pos + 1 < Hh) {
                const int OS2 = 3 + ((pos + 1) & 1);
                float* ofn = OF + ((pos + 1) & 1) * Cc * 16;
                #pragma unroll
                for (int k = 0; k < 5; k++) {
                    int idx = ytid + k * 256;
                    if (idx < Cc * 18) {
                        int ci = idx / 18, wi = idx % 18;
                        split_sts(&BHI[OS2 * SLOT_ELEMS + wi * CIST + ci],
                                  &BLO[OS2 * SLOT_ELEMS + wi * CIST + ci], pv[k]);
                        if (wi >= 1 && wi <= 16) ofn[ci * 16 + (wi - 1)] = pv[k];
                    }
                }
            }
        }

        __syncthreads();   // bar-B: row pos stores + next orig staged
        if (tid == 0) { __threadfence(); atomicExch(myflag, pos); }
    }
}

extern "C" void kernel_launch(void* const* d_in, const int* in_sizes, int n_in,
                              void* d_out, int out_size) {
    const float* X  = (const float*)d_in[0];
    const float* Wt = (const float*)d_in[1];
    const float* Bs = (const float*)d_in[2];
    float* Out = (float*)d_out;
    (void)in_sizes; (void)n_in; (void)out_size;

    cudaFuncSetAttribute(sc_main, cudaFuncAttributeMaxDynamicSharedMemorySize, SMEM_BYTES);

    sc_init_flags<<<1, 128>>>();
    sc_main<<<dim3(NT, Bb), NTHR, SMEM_BYTES>>>(X, Wt, Bs, Out);
}

// round 17
// speedup vs baseline: 1.0656x; 1.0656x over previous
#include <cuda_runtime.h>
#include <cuda_bf16.h>

// SequentialConv: B=8, C=64, H=192, W=256, 3x3, sequential row recurrence.
// Persistent wavefront: 8 batches x 16 width-tiles = 128 CTAs (all resident).
// Round 17: R15 exactly + ONE change: tanh.approx.f32 (MUFU) epilogue
// replacing tanhf (~25-instr chain x4 on the post-barrier critical path).
// R16 measured rel_err 4.5e-6 with this epilogue -> accuracy-safe.

#define Bb 8
#define Cc 64
#define Hh 192
#define Ww 256
#define NT 16
#define TW 16
#define NTHR 512
#define CIST 72                      // ci stride in row slots (bank-conflict-free)
#define SLOT_ELEMS (18 * CIST)       // bf16 per array per slot

#define AF_U32 36864                 // 4mi * 9khkw * 2hl * 4q * 32lane * 4reg
#define AF_BYTES (AF_U32 * 4)        // 147456
#define BARR_BYTES (5 * SLOT_ELEMS * 2)      // per array (hi / lo)
#define OF_FLOATS (2 * Cc * 16)              // orig-row f32 pingpong (interior)
#define RED_FLOATS (8 * 3 * 32 * 4)          // [mi*2+ni][prod 0..2][lane][4]
#define SMEM_BYTES (AF_BYTES + 2 * BARR_BYTES + OF_FLOATS * 4 + RED_FLOATS * 4)

typedef unsigned int u32;

__device__ int g_flags[Bb * NT];

__global__ void sc_init_flags() {
    int i = threadIdx.x;
    if (i < Bb * NT) g_flags[i] = 0;
}

__device__ __forceinline__ void split_sts(__nv_bfloat16* ph, __nv_bfloat16* pl, float v) {
    __nv_bfloat16 h = __float2bfloat16(v);
    *ph = h;
    *pl = __float2bfloat16(v - __bfloat162float(h));
}

__device__ __forceinline__ float tanh_fast(float x) {
    float y;
    asm("tanh.approx.f32 %0, %1;" : "=f"(y) : "f"(x));
    return y;
}

__device__ __forceinline__ void mma16816(float* d,
                                         u32 a0, u32 a1, u32 a2, u32 a3,
                                         u32 b0, u32 b1) {
    asm("mma.sync.aligned.m16n8k16.row.col.f32.bf16.bf16.f32 "
        "{%0,%1,%2,%3},{%4,%5,%6,%7},{%8,%9},{%0,%1,%2,%3};"
        : "+f"(d[0]), "+f"(d[1]), "+f"(d[2]), "+f"(d[3])
        : "r"(a0), "r"(a1), "r"(a2), "r"(a3), "r"(b0), "r"(b1));
}

// Both-ni plane over this warp's 2 K-chunks: A loaded once, used for 2 B tiles.
#define CONV2Q(d0, d1, SLOT, KH, KW)                                          \
  {                                                                           \
    const int khkw_ = (KH) * 3 + (KW);                                        \
    const __nv_bfloat16* bh0 = BHI + (SLOT) * SLOT_ELEMS + wrow0 + (KW) * CIST;\
    const __nv_bfloat16* bl0 = BLO + (SLOT) * SLOT_ELEMS + wrow0 + (KW) * CIST;\
    const __nv_bfloat16* bh1 = BHI + (SLOT) * SLOT_ELEMS + wrow1 + (KW) * CIST;\
    const __nv_bfloat16* bl1 = BLO + (SLOT) * SLOT_ELEMS + wrow1 + (KW) * CIST;\
    _Pragma("unroll")                                                         \
    for (int j = 0; j < 2; j++) {                                             \
      const int q_ = qb + j;                                                  \
      uint4 ah = AF4[(((mi * 9 + khkw_) * 2 + 0) * 4 + q_) * 32 + lane];      \
      uint4 al = AF4[(((mi * 9 + khkw_) * 2 + 1) * 4 + q_) * 32 + lane];      \
      u32 c0h = *(const u32*)(bh0 + q_ * 16);                                 \
      u32 c1h = *(const u32*)(bh0 + q_ * 16 + 8);                             \
      u32 c0l = *(const u32*)(bl0 + q_ * 16);                                 \
      u32 c1l = *(const u32*)(bl0 + q_ * 16 + 8);                             \
      mma16816(d0, ah.x, ah.y, ah.z, ah.w, c0h, c1h);                         \
      mma16816(d0, ah.x, ah.y, ah.z, ah.w, c0l, c1l);                         \
      mma16816(d0, al.x, al.y, al.z, al.w, c0h, c1h);                         \
      u32 e0h = *(const u32*)(bh1 + q_ * 16);                                 \
      u32 e1h = *(const u32*)(bh1 + q_ * 16 + 8);                             \
      u32 e0l = *(const u32*)(bl1 + q_ * 16);                                 \
      u32 e1l = *(const u32*)(bl1 + q_ * 16 + 8);                             \
      mma16816(d1, ah.x, ah.y, ah.z, ah.w, e0h, e1h);                         \
      mma16816(d1, ah.x, ah.y, ah.z, ah.w, e0l, e1l);                         \
      mma16816(d1, al.x, al.y, al.z, al.w, e0h, e1h);                         \
    }                                                                         \
  }

// One-ni plane over this warp's 2 K-chunks.
#define CONV1NI(dacc, SLOT, KH, KW, WROW)                                     \
  {                                                                           \
    const int khkw_ = (KH) * 3 + (KW);                                        \
    const __nv_bfloat16* bhk = BHI + (SLOT) * SLOT_ELEMS + (WROW) + (KW) * CIST;\
    const __nv_bfloat16* blk = BLO + (SLOT) * SLOT_ELEMS + (WROW) + (KW) * CIST;\
    _Pragma("unroll")                                                         \
    for (int j = 0; j < 2; j++) {                                             \
      const int q_ = qb + j;                                                  \
      uint4 ah = AF4[(((mi * 9 + khkw_) * 2 + 0) * 4 + q_) * 32 + lane];      \
      uint4 al = AF4[(((mi * 9 + khkw_) * 2 + 1) * 4 + q_) * 32 + lane];      \
      u32 b0h = *(const u32*)(bhk + q_ * 16);                                 \
      u32 b1h = *(const u32*)(bhk + q_ * 16 + 8);                             \
      u32 b0l = *(const u32*)(blk + q_ * 16);                                 \
      u32 b1l = *(const u32*)(blk + q_ * 16 + 8);                             \
      mma16816(dacc, ah.x, ah.y, ah.z, ah.w, b0h, b1h);                       \
      mma16816(dacc, ah.x, ah.y, ah.z, ah.w, b0l, b1l);                       \
      mma16816(dacc, al.x, al.y, al.z, al.w, b0h, b1h);                       \
    }                                                                         \
  }

// One-ni plane over ALL 4 K-chunks (post-bar halo plane, finalizer only).
#define CONV1NI_ALLQ(dacc, SLOT, KH, KW, WROW)                                \
  {                                                                           \
    const int khkw_ = (KH) * 3 + (KW);                                        \
    const __nv_bfloat16* bhk = BHI + (SLOT) * SLOT_ELEMS + (WROW) + (KW) * CIST;\
    const __nv_bfloat16* blk = BLO + (SLOT) * SLOT_ELEMS + (WROW) + (KW) * CIST;\
    _Pragma("unroll")                                                         \
    for (int q_ = 0; q_ < 4; q_++) {                                          \
      uint4 ah = AF4[(((mi * 9 + khkw_) * 2 + 0) * 4 + q_) * 32 + lane];      \
      uint4 al = AF4[(((mi * 9 + khkw_) * 2 + 1) * 4 + q_) * 32 + lane];      \
      u32 b0h = *(const u32*)(bhk + q_ * 16);                                 \
      u32 b1h = *(const u32*)(bhk + q_ * 16 + 8);                             \
      u32 b0l = *(const u32*)(blk + q_ * 16);                                 \
      u32 b1l = *(const u32*)(blk + q_ * 16 + 8);                             \
      mma16816(dacc, ah.x, ah.y, ah.z, ah.w, b0h, b1h);                       \
      mma16816(dacc, ah.x, ah.y, ah.z, ah.w, b0l, b1l);                       \
      mma16816(dacc, al.x, al.y, al.z, al.w, b0h, b1h);                       \
    }                                                                         \
  }

__global__ void __launch_bounds__(NTHR, 1) sc_main(
    const float* __restrict__ X, const float* __restrict__ Wt,
    const float* __restrict__ Bs, float* __restrict__ Out)
{
    extern __shared__ char smem[];
    u32*            AFu = (u32*)smem;                         // A fragments
    const uint4*    AF4 = (const uint4*)smem;
    __nv_bfloat16*  BHI = (__nv_bfloat16*)(smem + AF_BYTES);  // 5 slots [w][ci]
    __nv_bfloat16*  BLO = BHI + 5 * SLOT_ELEMS;
    float*          OF  = (float*)(BLO + 5 * SLOT_ELEMS);     // [2][64][16] f32
    float*          RED = OF + OF_FLOATS;                     // [8][3][32][4] f32

    const int tile = blockIdx.x;
    const int b    = blockIdx.y;
    const int w0   = tile * TW;
    const int tid  = threadIdx.x;
    const int wid  = tid >> 5;
    const int lane = tid & 31;
    const int g    = lane >> 2;
    const int tg   = lane & 3;
    const int grp  = wid >> 3;           // 0 = X, 1 = Y
    const int sub  = wid & 7;
    const int mi   = sub >> 1;           // co-tile 0..3
    const int qh   = sub & 1;            // K-half 0..1
    const int qb   = qh * 2;             // first q of this warp's half
    const int wrow0 = (g) * CIST + 2 * tg;          // ni=0 B base
    const int wrow1 = (8 + g) * CIST + 2 * tg;      // ni=1 B base

    // ---- Init A fragments: exact m16n8k16 A layout, hi/lo split. ----
    for (int i = tid; i < AF_U32; i += NTHR) {
        int r = i & 3; int ln = (i >> 2) & 31; int q = (i >> 7) & 3;
        int hl = (i >> 9) & 1; int t = i >> 10; int khkw = t % 9; int mI = t / 9;
        int gg = ln >> 2, tt = ln & 3;
        int co = mI * 16 + gg + ((r & 1) ? 8 : 0);
        int ci = q * 16 + 2 * tt + ((r & 2) ? 8 : 0);
        int kh = khkw / 3, kw = khkw % 3;
        float f0 = Wt[((co * Cc + ci) * 3 + kh) * 3 + kw];
        float f1 = Wt[((co * Cc + ci + 1) * 3 + kh) * 3 + kw];
        __nv_bfloat16 v0, v1;
        if (hl == 0) { v0 = __float2bfloat16(f0); v1 = __float2bfloat16(f1); }
        else {
            __nv_bfloat16 h0 = __float2bfloat16(f0), h1 = __float2bfloat16(f1);
            v0 = __float2bfloat16(f0 - __bfloat162float(h0));
            v1 = __float2bfloat16(f1 - __bfloat162float(h1));
        }
        AFu[i] = (u32)__bfloat16_as_ushort(v0) | ((u32)__bfloat16_as_ushort(v1) << 16);
    }

    const float* Xb = X   + (size_t)b * Cc * Hh * Ww;
    float*       Ob = Out + (size_t)b * Cc * Hh * Ww;

    // ---- Rows 0,1 (unchanged) -> slots 0,1 (bf16 split, incl halo); Out copy. ----
    for (int r = 0; r < 2; r++) {
        for (int i = tid; i < Cc * 18; i += NTHR) {
            int ci = i / 18, wi = i % 18; int w = w0 - 1 + wi;
            float v = (w >= 0 && w < Ww) ? Xb[(ci * Hh + r) * Ww + w] : 0.f;
            split_sts(&BHI[r * SLOT_ELEMS + wi * CIST + ci],
                      &BLO[r * SLOT_ELEMS + wi * CIST + ci], v);
        }
        for (int i = tid; i < Cc * TW; i += NTHR) {
            int ci = i / TW, wq = i % TW;
            Ob[(ci * Hh + r) * Ww + w0 + wq] = Xb[(ci * Hh + r) * Ww + w0 + wq];
        }
    }
    // Zero slot 2 halo cols (edge tiles keep all upd-slot halos 0 forever).
    if (tid < Cc) {
        BHI[2 * SLOT_ELEMS + tid] = __float2bfloat16(0.f);
        BLO[2 * SLOT_ELEMS + tid] = __float2bfloat16(0.f);
        BHI[2 * SLOT_ELEMS + 17 * CIST + tid] = __float2bfloat16(0.f);
        BLO[2 * SLOT_ELEMS + 17 * CIST + tid] = __float2bfloat16(0.f);
    }
    // Pre-stage orig row 2 (OS slot 3, OF half 0) before the loop.
    for (int i = tid; i < Cc * 18; i += NTHR) {
        int ci = i / 18, wi = i % 18; int w = w0 - 1 + wi;
        float v = (w >= 0 && w < Ww) ? Xb[(ci * Hh + 2) * Ww + w] : 0.f;
        split_sts(&BHI[3 * SLOT_ELEMS + wi * CIST + ci],
                  &BLO[3 * SLOT_ELEMS + wi * CIST + ci], v);
        if (wi >= 1 && wi <= 16) OF[ci * 16 + (wi - 1)] = v;
    }

    const float bs0 = __ldg(&Bs[mi * 16 + g]);
    const float bs1 = __ldg(&Bs[mi * 16 + g + 8]);

    int* myflag = &g_flags[b * NT + tile];
    int* lflag  = (tile > 0)      ? &g_flags[b * NT + tile - 1] : (int*)0;
    int* rflag  = (tile < NT - 1) ? &g_flags[b * NT + tile + 1] : (int*)0;

    __syncthreads();
    if (tid == 0) { __threadfence(); atomicExch(myflag, 1); }   // rows 0,1 published

    const int ytid = tid & 255;   // index within Y group (valid when grp==1)

    for (int pos = 2; pos < Hh; pos++) {
        const int OS = 3 + (pos & 1);            // orig slot (staged previous step)
        const int US = pos % 3;                  // write slot for updated row pos
        const int S0 = (pos + 1) % 3;            // updated row pos-2
        const int S1 = (pos + 2) % 3;            // updated row pos-1 (halo fresh)

        if (grp == 0) {
            // ---- X: halo + kh0/kh1kw1 (both ni, own q) pre-bar; own-ni halo
            //      plane (all q) + reduce + epilogue post-bar. ----
            float hv = 0.f; bool hL = false, hR = false;
            if (tid < Cc && lflag) {
                hL = true;
                while (*(volatile int*)lflag < pos - 1) __nanosleep(32);
                __threadfence();
                hv = __ldcg(&Ob[((size_t)tid * Hh + pos - 1) * Ww + w0 - 1]);
            } else if (tid >= 192 && tid < 192 + Cc && rflag) {
                hR = true;
                int ci = tid - 192;
                while (*(volatile int*)rflag < pos - 1) __nanosleep(32);
                __threadfence();
                hv = __ldcg(&Ob[((size_t)ci * Hh + pos - 1) * Ww + w0 + TW]);
            }

            float a0[4] = {0.f, 0.f, 0.f, 0.f};     // ni=0 accumulator
            float a1[4] = {0.f, 0.f, 0.f, 0.f};     // ni=1 accumulator
            CONV2Q(a0, a1, S0, 0, 0);
            CONV2Q(a0, a1, S0, 0, 1);
            CONV2Q(a0, a1, S0, 0, 2);
            CONV2Q(a0, a1, S1, 1, 1);               // kh1 kw1: interior for both ni

            // Exchange the other-ni partial (pre-bar complete by construction).
            {
                float* wp = RED + (((mi * 2 + (1 - qh)) * 3 + 0) * 32 + lane) * 4;
                if (qh == 0) *(float4*)wp = make_float4(a1[0], a1[1], a1[2], a1[3]);
                else         *(float4*)wp = make_float4(a0[0], a0[1], a0[2], a0[3]);
            }
            if (hL) split_sts(&BHI[S1 * SLOT_ELEMS + tid], &BLO[S1 * SLOT_ELEMS + tid], hv);
            if (hR) {
                int ci = tid - 192;
                split_sts(&BHI[S1 * SLOT_ELEMS + 17 * CIST + ci],
                          &BLO[S1 * SLOT_ELEMS + 17 * CIST + ci], hv);
            }
            __syncthreads();   // bar-A: halo + all RED partials in place

            // Post-bar: own-ni halo-dependent kh1 plane, ALL 4 q.
            float* own;
            if (qh == 0) { CONV1NI_ALLQ(a0, S1, 1, 0, wrow0); own = a0; }
            else         { CONV1NI_ALLQ(a1, S1, 1, 2, wrow1); own = a1; }

            // Reduce the 3 partials (X-other, Y-qh0, Y-qh1) for own half-tile.
            const float* rp = RED + (((mi * 2 + qh) * 3 + 0) * 32 + lane) * 4;
            float4 p0 = *(const float4*)(rp);
            float4 p1 = *(const float4*)(rp + 128);
            float4 p2 = *(const float4*)(rp + 256);
            float d0 = own[0] + p0.x + p1.x + p2.x;
            float d1 = own[1] + p0.y + p1.y + p2.y;
            float d2 = own[2] + p0.z + p1.z + p2.z;
            float d3 = own[3] + p0.w + p1.w + p2.w;

            const int co0 = mi * 16 + g;
            const int wq  = qh * 8 + 2 * tg;
            const float* ofp = OF + (pos & 1) * Cc * 16;
            float r00 = ofp[co0 * 16 + wq]           + tanh_fast(d0 + bs0);
            float r01 = ofp[co0 * 16 + wq + 1]       + tanh_fast(d1 + bs0);
            float r10 = ofp[(co0 + 8) * 16 + wq]     + tanh_fast(d2 + bs1);
            float r11 = ofp[(co0 + 8) * 16 + wq + 1] + tanh_fast(d3 + bs1);

            float* og = Ob + ((size_t)co0 * Hh + pos) * Ww + w0 + wq;
            *(float2*)og = make_float2(r00, r01);
            *(float2*)(og + 8 * (size_t)Hh * Ww) = make_float2(r10, r11);

            __nv_bfloat16* uh = BHI + US * SLOT_ELEMS;
            __nv_bfloat16* ul = BLO + US * SLOT_ELEMS;
            split_sts(&uh[(wq + 1) * CIST + co0],     &ul[(wq + 1) * CIST + co0],     r00);
            split_sts(&uh[(wq + 2) * CIST + co0],     &ul[(wq + 2) * CIST + co0],     r01);
            split_sts(&uh[(wq + 1) * CIST + co0 + 8], &ul[(wq + 1) * CIST + co0 + 8], r10);
            split_sts(&uh[(wq + 2) * CIST + co0 + 8], &ul[(wq + 2) * CIST + co0 + 8], r11);
        } else {
            // ---- Y: prefetch + kh2 (both ni) + kh1 interior (one ni each)
            //      pre-bar; RED push; staging post-bar. ----
            float pv[5];
            if (pos + 1 < Hh) {
                #pragma unroll
                for (int k = 0; k < 5; k++) {
                    int idx = ytid + k * 256;
                    if (idx < Cc * 18) {
                        int ci = idx / 18, wi = idx % 18; int w = w0 - 1 + wi;
                        pv[k] = (w >= 0 && w < Ww) ? __ldg(&Xb[(ci * Hh + pos + 1) * Ww + w]) : 0.f;
                    }
                }
            }

            float a0[4] = {0.f, 0.f, 0.f, 0.f};
            float a1[4] = {0.f, 0.f, 0.f, 0.f};
            CONV2Q(a0, a1, OS, 2, 0);
            CONV2Q(a0, a1, OS, 2, 1);
            CONV2Q(a0, a1, OS, 2, 2);
            CONV1NI(a0, S1, 1, 2, wrow0);   // kh1 ni0 kw2: interior (cols 2..9)
            CONV1NI(a1, S1, 1, 0, wrow1);   // kh1 ni1 kw0: interior (cols 8..15)

            *(float4*)(RED + (((mi * 2 + 0) * 3 + 1 + qh) * 32 + lane) * 4) =
                make_float4(a0[0], a0[1], a0[2], a0[3]);
            *(float4*)(RED + (((mi * 2 + 1) * 3 + 1 + qh) * 32 + lane) * 4) =
                make_float4(a1[0], a1[1], a1[2], a1[3]);
            __syncthreads();   // bar-A

            // Stage orig row pos+1 for the NEXT step.
            if (pos + 1 < Hh) {
                const int OS2 = 3 + ((pos + 1) & 1);
                float* ofn = OF + ((pos + 1) & 1) * Cc * 16;
                #pragma unroll
                for (int k = 0; k < 5; k++) {
                    int idx = ytid + k * 256;
                    if (idx < Cc * 18) {
                        int ci = idx / 18, wi = idx % 18;
                        split_sts(&BHI[OS2 * SLOT_ELEMS + wi * CIST + ci],
                                  &BLO[OS2 * SLOT_ELEMS + wi * CIST + ci], pv[k]);
                        if (wi >= 1 && wi <= 16) ofn[ci * 16 + (wi - 1)] = pv[k];
                    }
                }
            }
        }

        __syncthreads();   // bar-B: row pos stores + next orig staged
        if (tid == 0) { __threadfence(); atomicExch(myflag, pos); }
    }
}

extern "C" void kernel_launch(void* const* d_in, const int* in_sizes, int n_in,
                              void* d_out, int out_size) {
    const float* X  = (const float*)d_in[0];
    const float* Wt = (const float*)d_in[1];
    const float* Bs = (const float*)d_in[2];
    float* Out = (float*)d_out;
    (void)in_sizes; (void)n_in; (void)out_size;

    cudaFuncSetAttribute(sc_main, cudaFuncAttributeMaxDynamicSharedMemorySize, SMEM_BYTES);

    sc_init_flags<<<1, 128>>>();
    sc_main<<<dim3(NT, Bb), NTHR, SMEM_BYTES>>>(X, Wt, Bs, Out);
}